// round 6
// baseline (speedup 1.0000x reference)
#include <cuda_runtime.h>
#include <math.h>

// Problem constants (fixed by the dataset)
#define Bn  4
#define Sn  2048
#define En  512
#define Hn  8
#define DHn 8     // per-head dim
#define DPn 64    // H * DHn

// Scratch: [B, H, S, DHn] layouts for coalesced per-head access.
__device__ float g_Qp[Bn * Hn * Sn * DHn];
__device__ float g_Kp[Bn * Hn * Sn * DHn];
__device__ float g_Vp[Bn * Hn * Sn * DHn];
__device__ float g_Oc[Bn * Hn * Sn * DHn];

// ---------------------------------------------------------------------------
// Kernel 1: fused QKV projection.
// GEMM  X[8192,512] @ Wpacked[512,64] -> P, with P stored as [B,H,S,8].
// Block: 128 threads, tile M=64 x N=64, K-chunk 32.  grid.z selects Q/K/V.
// ---------------------------------------------------------------------------
__global__ __launch_bounds__(128) void qkv_proj_kernel(
    const float* __restrict__ Xq, const float* __restrict__ Xk,
    const float* __restrict__ Xv,
    const float* __restrict__ Wq, const float* __restrict__ Wk,
    const float* __restrict__ Wv)
{
    const int z = blockIdx.z;
    const float* __restrict__ X = (z == 0) ? Xq : ((z == 1) ? Xk : Xv);
    const float* __restrict__ W = (z == 0) ? Wq : ((z == 1) ? Wk : Wv);
    float* __restrict__ P = (z == 0) ? g_Qp : ((z == 1) ? g_Kp : g_Vp);

    __shared__ float As[32][68];   // [k][row], padded stride (68*4 bytes, 16B aligned)
    __shared__ float Ws[32][64];   // [k][col]

    const int tid  = threadIdx.x;
    const int tx   = tid & 15;     // 16 col groups * 4
    const int ty   = tid >> 4;     // 8 row groups * 8
    const int row0 = blockIdx.x * 64;

    float acc[8][4];
#pragma unroll
    for (int i = 0; i < 8; i++)
#pragma unroll
        for (int j = 0; j < 4; j++) acc[i][j] = 0.0f;

    for (int k0 = 0; k0 < En; k0 += 32) {
        // Load A tile (64 rows x 32 k), transposed into As[k][row]
#pragma unroll
        for (int i = 0; i < 4; i++) {
            int lin = tid + i * 128;       // 0..511 float4 slots
            int r   = lin >> 3;            // 0..63
            int kq  = lin & 7;             // float4 index along k
            float4 a = *(const float4*)&X[(size_t)(row0 + r) * En + k0 + kq * 4];
            As[kq * 4 + 0][r] = a.x;
            As[kq * 4 + 1][r] = a.y;
            As[kq * 4 + 2][r] = a.z;
            As[kq * 4 + 3][r] = a.w;
        }
        // Load W tile: Ws[kk][h*8+d] = W[h, k0+kk, d]   (W is [H,E,8])
#pragma unroll
        for (int i = 0; i < 2; i++) {
            int s  = tid + i * 128;        // 0..255 chunk slots
            int kk = s >> 3;               // 0..31
            int hh = s & 7;
            const float* src = W + (size_t)hh * (En * DHn) + (size_t)(k0 + kk) * DHn;
            float4 w0 = *(const float4*)(src);
            float4 w1 = *(const float4*)(src + 4);
            *(float4*)&Ws[kk][hh * 8]     = w0;
            *(float4*)&Ws[kk][hh * 8 + 4] = w1;
        }
        __syncthreads();

#pragma unroll
        for (int kk = 0; kk < 32; kk++) {
            float4 a0 = *(const float4*)&As[kk][ty * 8];
            float4 a1 = *(const float4*)&As[kk][ty * 8 + 4];
            float4 w  = *(const float4*)&Ws[kk][tx * 4];
            float av[8] = {a0.x, a0.y, a0.z, a0.w, a1.x, a1.y, a1.z, a1.w};
            float wv[4] = {w.x, w.y, w.z, w.w};
#pragma unroll
            for (int i = 0; i < 8; i++)
#pragma unroll
                for (int j = 0; j < 4; j++)
                    acc[i][j] = fmaf(av[i], wv[j], acc[i][j]);
        }
        __syncthreads();
    }

    // Write out into [B,H,S,8] layout. Each thread owns cols tx*4..tx*4+3
    // (all within one head since 4 | 8), rows row0+ty*8 .. +7.
    const int c4 = tx * 4;
    const int hh = c4 >> 3;
    const int dd = c4 & 7;
    const int b  = row0 >> 11;             // row0 / Sn  (64 | 2048, so constant per block)
    const int s0 = (row0 & (Sn - 1)) + ty * 8;
    float* dst = P + (((size_t)b * Hn + hh) * Sn + s0) * DHn + dd;
#pragma unroll
    for (int i = 0; i < 8; i++) {
        float4 v = make_float4(acc[i][0], acc[i][1], acc[i][2], acc[i][3]);
        *(float4*)(dst + (size_t)i * DHn) = v;
    }
}

// ---------------------------------------------------------------------------
// Kernel 2: causal flash attention, d_head = 8.
// One block = (b, h, 128-query tile); one thread = one query row.
// Online softmax in 8-key chunks (one rescale per chunk instead of per key).
// Replicates the reference quirk: score masked if raw score == 0.0 as well.
// ---------------------------------------------------------------------------
__global__ __launch_bounds__(128) void attn_kernel()
{
    // Reverse x so the heaviest (largest qb) blocks launch first.
    const int qb  = (int)gridDim.x - 1 - (int)blockIdx.x;
    const int h   = blockIdx.y;
    const int b   = blockIdx.z;
    const int tid = threadIdx.x;

    __shared__ float4 ksm[256];   // [key][2] -> 128 keys x 8 floats
    __shared__ float4 vsm[256];

    const size_t head = ((size_t)b * Hn + h) * Sn;
    const int    qi   = qb * 128 + tid;

    const float* Qh = g_Qp + (head + qi) * DHn;
    float4 q0 = *(const float4*)(Qh);
    float4 q1 = *(const float4*)(Qh + 4);
    const float sc = 0.35355339059327373f;  // 1/sqrt(8); pre-scale Q (s==0 iff raw==0)
    q0.x *= sc; q0.y *= sc; q0.z *= sc; q0.w *= sc;
    q1.x *= sc; q1.y *= sc; q1.z *= sc; q1.w *= sc;

    float4 o0 = make_float4(0.f, 0.f, 0.f, 0.f);
    float4 o1 = make_float4(0.f, 0.f, 0.f, 0.f);
    float  m = -1e30f;   // finite sentinel avoids inf-inf NaN paths
    float  l = 0.0f;
    const float NEG_INF = -INFINITY;

    for (int kb = 0; kb <= qb; kb++) {
        const float* Kr = g_Kp + (head + (size_t)kb * 128 + tid) * DHn;
        const float* Vr = g_Vp + (head + (size_t)kb * 128 + tid) * DHn;
        ksm[tid * 2]     = *(const float4*)(Kr);
        ksm[tid * 2 + 1] = *(const float4*)(Kr + 4);
        vsm[tid * 2]     = *(const float4*)(Vr);
        vsm[tid * 2 + 1] = *(const float4*)(Vr + 4);
        __syncthreads();

        const bool diag = (kb == qb);
#pragma unroll 1
        for (int c = 0; c < 16; c++) {
            float s[8];
#pragma unroll
            for (int jj = 0; jj < 8; jj++) {
                int j = c * 8 + jj;
                float4 k0 = ksm[j * 2];
                float4 k1 = ksm[j * 2 + 1];
                float v = q0.x * k0.x;
                v = fmaf(q0.y, k0.y, v);
                v = fmaf(q0.z, k0.z, v);
                v = fmaf(q0.w, k0.w, v);
                v = fmaf(q1.x, k1.x, v);
                v = fmaf(q1.y, k1.y, v);
                v = fmaf(q1.z, k1.z, v);
                v = fmaf(q1.w, k1.w, v);
                bool msk = (v == 0.0f);          // tril(s)==0 quirk
                if (diag) msk |= (j > tid);      // causal: key idx > query idx
                s[jj] = msk ? NEG_INF : v;
            }
            float mc = s[0];
#pragma unroll
            for (int jj = 1; jj < 8; jj++) mc = fmaxf(mc, s[jj]);
            if (mc > m) {
                float alpha = __expf(m - mc);
                l *= alpha;
                o0.x *= alpha; o0.y *= alpha; o0.z *= alpha; o0.w *= alpha;
                o1.x *= alpha; o1.y *= alpha; o1.z *= alpha; o1.w *= alpha;
                m = mc;
            }
#pragma unroll
            for (int jj = 0; jj < 8; jj++) {
                int j = c * 8 + jj;
                float p = __expf(s[jj] - m);     // masked -> exp(-inf) = 0
                l += p;
                float4 v0 = vsm[j * 2];
                float4 v1 = vsm[j * 2 + 1];
                o0.x = fmaf(p, v0.x, o0.x);
                o0.y = fmaf(p, v0.y, o0.y);
                o0.z = fmaf(p, v0.z, o0.z);
                o0.w = fmaf(p, v0.w, o0.w);
                o1.x = fmaf(p, v1.x, o1.x);
                o1.y = fmaf(p, v1.y, o1.y);
                o1.z = fmaf(p, v1.z, o1.z);
                o1.w = fmaf(p, v1.w, o1.w);
            }
        }
        __syncthreads();
    }

    float inv = 1.0f / l;
    o0.x *= inv; o0.y *= inv; o0.z *= inv; o0.w *= inv;
    o1.x *= inv; o1.y *= inv; o1.z *= inv; o1.w *= inv;
    float* dst = g_Oc + (head + qi) * DHn;
    *(float4*)(dst)     = o0;
    *(float4*)(dst + 4) = o1;
}

// ---------------------------------------------------------------------------
// Kernel 3: output projection.  Oc[8192,64] @ Wo[64,512] + bo -> out[8192,512]
// Block: 256 threads, tile 64x64, K=64 in a single smem pass.
// ---------------------------------------------------------------------------
__global__ __launch_bounds__(256) void out_proj_kernel(
    const float* __restrict__ Wo, const float* __restrict__ bo,
    float* __restrict__ out)
{
    __shared__ float As[64][68];   // [c][row]
    __shared__ float Ws[64][68];   // [c][col]

    const int tid  = threadIdx.x;
    const int tx   = tid & 15;     // 16 col groups * 4
    const int ty   = tid >> 4;     // 16 row groups * 4
    const int row0 = blockIdx.y * 64;
    const int col0 = blockIdx.x * 64;
    const int b    = row0 >> 11;
    const int s0   = row0 & (Sn - 1);

    // Load Oc tile, gathering from [B,H,S,8] back into packed cols c = h*8+d
#pragma unroll
    for (int i = 0; i < 4; i++) {
        int lin = tid + i * 256;   // 0..1023 float4 slots (64 rows x 16)
        int r   = lin >> 4;        // 0..63
        int cq  = lin & 15;        // packed-col float4 index
        int hh  = cq >> 1;
        int dd  = (cq & 1) * 4;
        float4 a = *(const float4*)(g_Oc +
                     (((size_t)b * Hn + hh) * Sn + s0 + r) * DHn + dd);
        As[cq * 4 + 0][r] = a.x;
        As[cq * 4 + 1][r] = a.y;
        As[cq * 4 + 2][r] = a.z;
        As[cq * 4 + 3][r] = a.w;
    }
    // Load Wo tile: Ws[c][n] = Wo[c, col0+n]
#pragma unroll
    for (int i = 0; i < 4; i++) {
        int lin = tid + i * 256;
        int c   = lin >> 4;
        int nq  = lin & 15;
        float4 w = *(const float4*)(Wo + (size_t)c * En + col0 + nq * 4);
        *(float4*)&Ws[c][nq * 4] = w;
    }
    __syncthreads();

    float acc[4][4];
#pragma unroll
    for (int i = 0; i < 4; i++)
#pragma unroll
        for (int j = 0; j < 4; j++) acc[i][j] = 0.0f;

#pragma unroll 8
    for (int c = 0; c < 64; c++) {
        float4 a = *(const float4*)&As[c][ty * 4];
        float4 w = *(const float4*)&Ws[c][tx * 4];
        float av[4] = {a.x, a.y, a.z, a.w};
        float wv[4] = {w.x, w.y, w.z, w.w};
#pragma unroll
        for (int i = 0; i < 4; i++)
#pragma unroll
            for (int j = 0; j < 4; j++)
                acc[i][j] = fmaf(av[i], wv[j], acc[i][j]);
    }

    float4 bias = *(const float4*)(bo + col0 + tx * 4);
#pragma unroll
    for (int i = 0; i < 4; i++) {
        float4 r;
        r.x = acc[i][0] + bias.x;
        r.y = acc[i][1] + bias.y;
        r.z = acc[i][2] + bias.z;
        r.w = acc[i][3] + bias.w;
        *(float4*)(out + (size_t)(row0 + ty * 4 + i) * En + col0 + tx * 4) = r;
    }
}

// ---------------------------------------------------------------------------
extern "C" void kernel_launch(void* const* d_in, const int* in_sizes, int n_in,
                              void* d_out, int out_size)
{
    const float* query = (const float*)d_in[0];
    const float* key_  = (const float*)d_in[1];
    const float* value = (const float*)d_in[2];

    // Locate weights robustly by element count (padding_mask = 16777216 bools,
    // decoder_mask = 1 scalar are skipped regardless of presence/ordering).
    // Metadata order among equal-size (32768) entries: Wq, Wk, Wv, Wo.
    const float* w32[4] = {0, 0, 0, 0};
    int nw = 0;
    const float* bo = 0;
    for (int i = 3; i < n_in; i++) {
        if (in_sizes[i] == Hn * En * DHn && nw < 4) {   // 32768 (also DPn*En)
            w32[nw++] = (const float*)d_in[i];
        } else if (in_sizes[i] == En) {
            bo = (const float*)d_in[i];
        }
    }
    const float* Wq = w32[0];
    const float* Wk = w32[1];
    const float* Wv = w32[2];
    const float* Wo = w32[3];
    float* out = (float*)d_out;

    qkv_proj_kernel<<<dim3((Bn * Sn) / 64, 1, 3), 128>>>(query, key_, value,
                                                         Wq, Wk, Wv);
    attn_kernel<<<dim3(Sn / 128, Hn, Bn), 128>>>();
    out_proj_kernel<<<dim3(En / 64, (Bn * Sn) / 64), 256>>>(Wo, bo, out);
}

// round 7
// speedup vs baseline: 1.0006x; 1.0006x over previous
#include <cuda_runtime.h>
#include <math.h>

// Problem constants (fixed by the dataset)
#define Bn  4
#define Sn  2048
#define En  512
#define Hn  8
#define DHn 8     // per-head dim
#define DPn 64    // H * DHn

// Scratch: [B, H, S, DHn] layouts for coalesced per-head access.
__device__ float g_Qp[Bn * Hn * Sn * DHn];
__device__ float g_Kp[Bn * Hn * Sn * DHn];
__device__ float g_Vp[Bn * Hn * Sn * DHn];
__device__ float g_Oc[Bn * Hn * Sn * DHn];

// ---------------------------------------------------------------------------
// Kernel 1: fused QKV projection.
// GEMM  X[8192,512] @ Wpacked[512,64] -> P, with P stored as [B,H,S,8].
// Block: 128 threads, tile M=64 x N=64, K-chunk 32.  grid.z selects Q/K/V.
// ---------------------------------------------------------------------------
__global__ __launch_bounds__(128) void qkv_proj_kernel(
    const float* __restrict__ Xq, const float* __restrict__ Xk,
    const float* __restrict__ Xv,
    const float* __restrict__ Wq, const float* __restrict__ Wk,
    const float* __restrict__ Wv)
{
    const int z = blockIdx.z;
    const float* __restrict__ X = (z == 0) ? Xq : ((z == 1) ? Xk : Xv);
    const float* __restrict__ W = (z == 0) ? Wq : ((z == 1) ? Wk : Wv);
    float* __restrict__ P = (z == 0) ? g_Qp : ((z == 1) ? g_Kp : g_Vp);

    __shared__ float As[32][68];   // [k][row], padded stride (68*4 bytes, 16B aligned)
    __shared__ float Ws[32][64];   // [k][col]

    const int tid  = threadIdx.x;
    const int tx   = tid & 15;     // 16 col groups * 4
    const int ty   = tid >> 4;     // 8 row groups * 8
    const int row0 = blockIdx.x * 64;

    float acc[8][4];
#pragma unroll
    for (int i = 0; i < 8; i++)
#pragma unroll
        for (int j = 0; j < 4; j++) acc[i][j] = 0.0f;

    for (int k0 = 0; k0 < En; k0 += 32) {
        // Load A tile (64 rows x 32 k), transposed into As[k][row]
#pragma unroll
        for (int i = 0; i < 4; i++) {
            int lin = tid + i * 128;       // 0..511 float4 slots
            int r   = lin >> 3;            // 0..63
            int kq  = lin & 7;             // float4 index along k
            float4 a = *(const float4*)&X[(size_t)(row0 + r) * En + k0 + kq * 4];
            As[kq * 4 + 0][r] = a.x;
            As[kq * 4 + 1][r] = a.y;
            As[kq * 4 + 2][r] = a.z;
            As[kq * 4 + 3][r] = a.w;
        }
        // Load W tile: Ws[kk][h*8+d] = W[h, k0+kk, d]   (W is [H,E,8])
#pragma unroll
        for (int i = 0; i < 2; i++) {
            int s  = tid + i * 128;        // 0..255 chunk slots
            int kk = s >> 3;               // 0..31
            int hh = s & 7;
            const float* src = W + (size_t)hh * (En * DHn) + (size_t)(k0 + kk) * DHn;
            float4 w0 = *(const float4*)(src);
            float4 w1 = *(const float4*)(src + 4);
            *(float4*)&Ws[kk][hh * 8]     = w0;
            *(float4*)&Ws[kk][hh * 8 + 4] = w1;
        }
        __syncthreads();

#pragma unroll
        for (int kk = 0; kk < 32; kk++) {
            float4 a0 = *(const float4*)&As[kk][ty * 8];
            float4 a1 = *(const float4*)&As[kk][ty * 8 + 4];
            float4 w  = *(const float4*)&Ws[kk][tx * 4];
            float av[8] = {a0.x, a0.y, a0.z, a0.w, a1.x, a1.y, a1.z, a1.w};
            float wv[4] = {w.x, w.y, w.z, w.w};
#pragma unroll
            for (int i = 0; i < 8; i++)
#pragma unroll
                for (int j = 0; j < 4; j++)
                    acc[i][j] = fmaf(av[i], wv[j], acc[i][j]);
        }
        __syncthreads();
    }

    // Write out into [B,H,S,8] layout. Each thread owns cols tx*4..tx*4+3
    // (all within one head since 4 | 8), rows row0+ty*8 .. +7.
    const int c4 = tx * 4;
    const int hh = c4 >> 3;
    const int dd = c4 & 7;
    const int b  = row0 >> 11;             // row0 / Sn  (64 | 2048, so constant per block)
    const int s0 = (row0 & (Sn - 1)) + ty * 8;
    float* dst = P + (((size_t)b * Hn + hh) * Sn + s0) * DHn + dd;
#pragma unroll
    for (int i = 0; i < 8; i++) {
        float4 v = make_float4(acc[i][0], acc[i][1], acc[i][2], acc[i][3]);
        *(float4*)(dst + (size_t)i * DHn) = v;
    }
}

// ---------------------------------------------------------------------------
// Kernel 2: causal flash attention, d_head = 8.
// One block = (b, h, 128-query tile); one thread = one query row.
// Online softmax in 8-key chunks (one rescale per chunk instead of per key).
// Replicates the reference quirk: score masked if raw score == 0.0 as well.
// ---------------------------------------------------------------------------
__global__ __launch_bounds__(128) void attn_kernel()
{
    // Reverse x so the heaviest (largest qb) blocks launch first.
    const int qb  = (int)gridDim.x - 1 - (int)blockIdx.x;
    const int h   = blockIdx.y;
    const int b   = blockIdx.z;
    const int tid = threadIdx.x;

    __shared__ float4 ksm[256];   // [key][2] -> 128 keys x 8 floats
    __shared__ float4 vsm[256];

    const size_t head = ((size_t)b * Hn + h) * Sn;
    const int    qi   = qb * 128 + tid;

    const float* Qh = g_Qp + (head + qi) * DHn;
    float4 q0 = *(const float4*)(Qh);
    float4 q1 = *(const float4*)(Qh + 4);
    const float sc = 0.35355339059327373f;  // 1/sqrt(8); pre-scale Q (s==0 iff raw==0)
    q0.x *= sc; q0.y *= sc; q0.z *= sc; q0.w *= sc;
    q1.x *= sc; q1.y *= sc; q1.z *= sc; q1.w *= sc;

    float4 o0 = make_float4(0.f, 0.f, 0.f, 0.f);
    float4 o1 = make_float4(0.f, 0.f, 0.f, 0.f);
    float  m = -1e30f;   // finite sentinel avoids inf-inf NaN paths
    float  l = 0.0f;
    const float NEG_INF = -INFINITY;

    for (int kb = 0; kb <= qb; kb++) {
        const float* Kr = g_Kp + (head + (size_t)kb * 128 + tid) * DHn;
        const float* Vr = g_Vp + (head + (size_t)kb * 128 + tid) * DHn;
        ksm[tid * 2]     = *(const float4*)(Kr);
        ksm[tid * 2 + 1] = *(const float4*)(Kr + 4);
        vsm[tid * 2]     = *(const float4*)(Vr);
        vsm[tid * 2 + 1] = *(const float4*)(Vr + 4);
        __syncthreads();

        const bool diag = (kb == qb);
#pragma unroll 1
        for (int c = 0; c < 16; c++) {
            float s[8];
#pragma unroll
            for (int jj = 0; jj < 8; jj++) {
                int j = c * 8 + jj;
                float4 k0 = ksm[j * 2];
                float4 k1 = ksm[j * 2 + 1];
                float v = q0.x * k0.x;
                v = fmaf(q0.y, k0.y, v);
                v = fmaf(q0.z, k0.z, v);
                v = fmaf(q0.w, k0.w, v);
                v = fmaf(q1.x, k1.x, v);
                v = fmaf(q1.y, k1.y, v);
                v = fmaf(q1.z, k1.z, v);
                v = fmaf(q1.w, k1.w, v);
                bool msk = (v == 0.0f);          // tril(s)==0 quirk
                if (diag) msk |= (j > tid);      // causal: key idx > query idx
                s[jj] = msk ? NEG_INF : v;
            }
            float mc = s[0];
#pragma unroll
            for (int jj = 1; jj < 8; jj++) mc = fmaxf(mc, s[jj]);
            if (mc > m) {
                float alpha = __expf(m - mc);
                l *= alpha;
                o0.x *= alpha; o0.y *= alpha; o0.z *= alpha; o0.w *= alpha;
                o1.x *= alpha; o1.y *= alpha; o1.z *= alpha; o1.w *= alpha;
                m = mc;
            }
#pragma unroll
            for (int jj = 0; jj < 8; jj++) {
                int j = c * 8 + jj;
                float p = __expf(s[jj] - m);     // masked -> exp(-inf) = 0
                l += p;
                float4 v0 = vsm[j * 2];
                float4 v1 = vsm[j * 2 + 1];
                o0.x = fmaf(p, v0.x, o0.x);
                o0.y = fmaf(p, v0.y, o0.y);
                o0.z = fmaf(p, v0.z, o0.z);
                o0.w = fmaf(p, v0.w, o0.w);
                o1.x = fmaf(p, v1.x, o1.x);
                o1.y = fmaf(p, v1.y, o1.y);
                o1.z = fmaf(p, v1.z, o1.z);
                o1.w = fmaf(p, v1.w, o1.w);
            }
        }
        __syncthreads();
    }

    float inv = 1.0f / l;
    o0.x *= inv; o0.y *= inv; o0.z *= inv; o0.w *= inv;
    o1.x *= inv; o1.y *= inv; o1.z *= inv; o1.w *= inv;
    float* dst = g_Oc + (head + qi) * DHn;
    *(float4*)(dst)     = o0;
    *(float4*)(dst + 4) = o1;
}

// ---------------------------------------------------------------------------
// Kernel 3: output projection.  Oc[8192,64] @ Wo[64,512] + bo -> out[8192,512]
// Block: 256 threads, tile 64x64, K=64 in a single smem pass.
// ---------------------------------------------------------------------------
__global__ __launch_bounds__(256) void out_proj_kernel(
    const float* __restrict__ Wo, const float* __restrict__ bo,
    float* __restrict__ out)
{
    __shared__ float As[64][68];   // [c][row]
    __shared__ float Ws[64][68];   // [c][col]

    const int tid  = threadIdx.x;
    const int tx   = tid & 15;     // 16 col groups * 4
    const int ty   = tid >> 4;     // 16 row groups * 4
    const int row0 = blockIdx.y * 64;
    const int col0 = blockIdx.x * 64;
    const int b    = row0 >> 11;
    const int s0   = row0 & (Sn - 1);

    // Load Oc tile, gathering from [B,H,S,8] back into packed cols c = h*8+d
#pragma unroll
    for (int i = 0; i < 4; i++) {
        int lin = tid + i * 256;   // 0..1023 float4 slots (64 rows x 16)
        int r   = lin >> 4;        // 0..63
        int cq  = lin & 15;        // packed-col float4 index
        int hh  = cq >> 1;
        int dd  = (cq & 1) * 4;
        float4 a = *(const float4*)(g_Oc +
                     (((size_t)b * Hn + hh) * Sn + s0 + r) * DHn + dd);
        As[cq * 4 + 0][r] = a.x;
        As[cq * 4 + 1][r] = a.y;
        As[cq * 4 + 2][r] = a.z;
        As[cq * 4 + 3][r] = a.w;
    }
    // Load Wo tile: Ws[c][n] = Wo[c, col0+n]
#pragma unroll
    for (int i = 0; i < 4; i++) {
        int lin = tid + i * 256;
        int c   = lin >> 4;
        int nq  = lin & 15;
        float4 w = *(const float4*)(Wo + (size_t)c * En + col0 + nq * 4);
        *(float4*)&Ws[c][nq * 4] = w;
    }
    __syncthreads();

    float acc[4][4];
#pragma unroll
    for (int i = 0; i < 4; i++)
#pragma unroll
        for (int j = 0; j < 4; j++) acc[i][j] = 0.0f;

#pragma unroll 8
    for (int c = 0; c < 64; c++) {
        float4 a = *(const float4*)&As[c][ty * 4];
        float4 w = *(const float4*)&Ws[c][tx * 4];
        float av[4] = {a.x, a.y, a.z, a.w};
        float wv[4] = {w.x, w.y, w.z, w.w};
#pragma unroll
        for (int i = 0; i < 4; i++)
#pragma unroll
            for (int j = 0; j < 4; j++)
                acc[i][j] = fmaf(av[i], wv[j], acc[i][j]);
    }

    float4 bias = *(const float4*)(bo + col0 + tx * 4);
#pragma unroll
    for (int i = 0; i < 4; i++) {
        float4 r;
        r.x = acc[i][0] + bias.x;
        r.y = acc[i][1] + bias.y;
        r.z = acc[i][2] + bias.z;
        r.w = acc[i][3] + bias.w;
        *(float4*)(out + (size_t)(row0 + ty * 4 + i) * En + col0 + tx * 4) = r;
    }
}

// ---------------------------------------------------------------------------
extern "C" void kernel_launch(void* const* d_in, const int* in_sizes, int n_in,
                              void* d_out, int out_size)
{
    const float* query = (const float*)d_in[0];
    const float* key_  = (const float*)d_in[1];
    const float* value = (const float*)d_in[2];

    // Locate weights robustly by element count (padding_mask = 16777216 bools,
    // decoder_mask = 1 scalar are skipped regardless of presence/ordering).
    // Metadata order among equal-size (32768) entries: Wq, Wk, Wv, Wo.
    const float* w32[4] = {0, 0, 0, 0};
    int nw = 0;
    const float* bo = 0;
    for (int i = 3; i < n_in; i++) {
        if (in_sizes[i] == Hn * En * DHn && nw < 4) {   // 32768 (also DPn*En)
            w32[nw++] = (const float*)d_in[i];
        } else if (in_sizes[i] == En) {
            bo = (const float*)d_in[i];
        }
    }
    const float* Wq = w32[0];
    const float* Wk = w32[1];
    const float* Wv = w32[2];
    const float* Wo = w32[3];
    float* out = (float*)d_out;

    qkv_proj_kernel<<<dim3((Bn * Sn) / 64, 1, 3), 128>>>(query, key_, value,
                                                         Wq, Wk, Wv);
    attn_kernel<<<dim3(Sn / 128, Hn, Bn), 128>>>();
    out_proj_kernel<<<dim3(En / 64, (Bn * Sn) / 64), 256>>>(Wo, bo, out);
}